// round 15
// baseline (speedup 1.0000x reference)
#include <cuda_runtime.h>

#define TSTEPS 2048
#define BSIZE  8192
#define HH     0.01f
#define NG     (TSTEPS / 4)   // 512 groups of 4 steps
#define PD     4              // prefetch distance (groups)

typedef unsigned long long u64;

__device__ __forceinline__ float ex2f(float x) {
    float y; asm("ex2.approx.ftz.f32 %0, %1;" : "=f"(y) : "f"(x)); return y;
}
__device__ __forceinline__ float rcpf(float x) {
    float y; asm("rcp.approx.ftz.f32 %0, %1;" : "=f"(y) : "f"(x)); return y;
}
__device__ __forceinline__ u64 pk(float lo, float hi) {
    u64 r; asm("mov.b64 %0, {%1, %2};" : "=l"(r) : "f"(lo), "f"(hi)); return r;
}
__device__ __forceinline__ void upk(float& lo, float& hi, u64 v) {
    asm("mov.b64 {%0, %1}, %2;" : "=f"(lo), "=f"(hi) : "l"(v));
}
__device__ __forceinline__ u64 fma2(u64 a, u64 b, u64 c) {
    u64 d; asm("fma.rn.f32x2 %0, %1, %2, %3;" : "=l"(d) : "l"(a), "l"(b), "l"(c)); return d;
}
__device__ __forceinline__ u64 add2(u64 a, u64 b) {
    u64 d; asm("add.rn.f32x2 %0, %1, %2;" : "=l"(d) : "l"(a), "l"(b)); return d;
}
__device__ __forceinline__ u64 mul2(u64 a, u64 b) {
    u64 d; asm("mul.rn.f32x2 %0, %1, %2;" : "=l"(d) : "l"(a), "l"(b)); return d;
}

struct CP {
    u64 NEG1, E2, HH2, HHb, Cp;
    // Lane-matched pairs (coeffs scaled by -log2e), proven in R13:
    //   q1(z) = a11 z1 + a12 z2 + a13 z3 + a14 z4 + bm1
    //   q2(z) = a22 z2 +        a23 z3 + a24 z4 + bm2
    //   q3(z) = a33 z3 + a34 z4 + bm3 ;  q4(z) = a44 z4 + bm4
    // packed with Z12=(z1,z2), Z12s=(z2,z1), Z34=(z3,z4), Z34s=(z4,z3):
    //   Q12 = Z12*CA + Z12s*CB + Z34*CC + Z34s*CD + Bm12
    //   Q34 = Z34*CE + Z34s*CF + Bm34
    u64 CA, CB, CC, CD, Bm12, CE, CF, Bm34, Cbm0;
    u64 CAB;            // CA + CB lane-wise = (a11+a12, a22) — for d=(hk,hk,..)
    float K1, K2;
};

// One step. delta = rcp(1 + ex2(phiS)), phiS loop-carried scalar.
// KEY: q(z_new) = q(zm) + delta * U*d  (matvec is linear; z_new = zm + delta*d)
// so BOTH trees (on zm and on d) run in the MUFU shadow. Post-rcp chain:
// DEL2 mov -> {X,Hh,Q12n,Q34n} (parallel fma2) -> PP inner -> PP outer -> fadd
// = ~21 cyc. Full chain ~57; slot floor ~62.
template<bool ADDSC>
__device__ __forceinline__ void stepP(const CP& c, float w1, float w2,
                                      u64& X, u64& Hh, float& phiS,
                                      u64& accQ2, float& accR, float& accT)
{
    float e = ex2f(phiS);                     // MUFU #1, issues first

    // ---- shadow geometry (zm, d and both trees fit in the MUFU shadows) ----
    u64 DX = fma2(Hh, c.NEG1, X);             // d34 = (dx1, dx2) = X - H
    float dx1, dx2; upk(dx1, dx2, DX);
    float h1, h2;   upk(h1, h2, Hh);
    float x1s, x2s; upk(x1s, x2s, X);
    u64 Xs = pk(x2s, x1s);

    float kuh = fmaf(c.K2, h2, c.K1 * h1);    // K . x_hat
    float kdx = fmaf(c.K2, dx2, c.K1 * dx1);  // K . (x - x_hat)
    float hkdx = 0.01f * kdx;                 // delta-coefficient of x'

    u64 W  = pk(w1, w2);
    u64 WC = add2(W, c.Cp);                   // + (h^2/2, -h^2)
    u64 T1 = fma2(X, c.E2, WC);               // 0.98*x + w + C
    u64 BASE = fma2(Xs, c.HH2, T1);           // + 0.01*x_swapped
    u64 KUH2 = pk(kuh, kuh);
    u64 BXu  = fma2(KUH2, c.HHb, BASE);       // zm12: x' = BXu + delta*hk
    u64 HKp  = pk(hkdx, hkdx);                // d12 (symmetric pair)

    // zm = (BXu, Hh_old), d = (HKp, DX): shadow swaps
    float bxu1, bxu2; upk(bxu1, bxu2, BXu);
    u64 BXuS = pk(bxu2, bxu1);
    u64 HhS  = pk(h2, h1);
    u64 DXs  = pk(dx2, dx1);

    // q(zm) = U*zm + m  (6 packed)
    u64 QZM12 = fma2(BXu, c.CA,
                fma2(BXuS, c.CB,
                fma2(Hh, c.CC,
                fma2(HhS, c.CD, c.Bm12))));
    u64 QZM34 = fma2(Hh, c.CE, fma2(HhS, c.CF, c.Bm34));
    // U*d (no m). d12s == d12 = (hk,hk) -> CA,CB merge into CAB. (5 packed)
    u64 UD12 = fma2(HKp, c.CAB, fma2(DX, c.CC, mul2(DXs, c.CD)));
    u64 UD34 = fma2(DX, c.CE, mul2(DXs, c.CF));

    if (ADDSC) {
        accQ2 = fma2(X, X, accQ2);            // packed sum of x^2
        float kx = kuh + kdx;                 // u_s = K . x (exact)
        accR = fmaf(kx, kx, accR);            // 0.1 applied once at the end
    }

    float den   = 1.0f + e;
    float delta = rcpf(den);                  // MUFU #2
    if (ADDSC) accT = accT + delta;           // off the chain

    // ---- post-rcp: broadcast, then 4 PARALLEL fma2, dot, horizontal ----
    u64 DEL2 = pk(delta, delta);
    X  = fma2(DEL2, HKp, BXu);                // new state
    Hh = fma2(DEL2, DX, Hh);
    u64 Q12n = fma2(DEL2, UD12, QZM12);       // q(z_new), forwarded
    u64 Q34n = fma2(DEL2, UD34, QZM34);
    u64 PP = fma2(X, Q12n, fma2(Hh, Q34n, c.Cbm0));
    float plo, phi_; upk(plo, phi_, PP);
    phiS = plo + phi_;                        // scalar carried into next step
}

__global__ void __launch_bounds__(64, 1) cstr_traj_kernel(
    const float* __restrict__ w,   // (B, 2, T)
    const float* __restrict__ K,   // (1, 2)
    const float* __restrict__ L,   // (4, 4)
    const float* __restrict__ M,   // (1, 4)
    const float* __restrict__ Mo,  // (1, 1)
    float* __restrict__ out)       // (B,)
{
    int b = blockIdx.x * blockDim.x + threadIdx.x;

    const float s = -1.44269504088896340736f;  // -log2(e), folded into phi
    float K1 = __ldg(K), K2 = __ldg(K + 1);
    float l[16];
#pragma unroll
    for (int i = 0; i < 16; i++) l[i] = __ldg(L + i);
    float a11 = s * l[0],           a22 = s * l[5];
    float a33 = s * l[10],          a44 = s * l[15];
    float a12 = s * (l[1] + l[4]),  a13 = s * (l[2] + l[8]);
    float a14 = s * (l[3] + l[12]), a23 = s * (l[6] + l[9]);
    float a24 = s * (l[7] + l[13]), a34 = s * (l[11] + l[14]);
    float bm1 = s * __ldg(M),       bm2 = s * __ldg(M + 1);
    float bm3 = s * __ldg(M + 2),   bm4 = s * __ldg(M + 3);
    float bm0 = s * __ldg(Mo);

    CP c;
    c.K1 = K1; c.K2 = K2;
    c.NEG1 = pk(-1.0f, -1.0f);
    c.E2   = pk(0.98f, 0.98f);
    c.HH2  = pk(HH, HH);
    c.HHb  = pk(HH, HH);
    c.Cp   = pk(0.5f * HH * HH, -HH * HH);      // (+h^2/2, -h^2)
    c.CA = pk(a11, a22);    // * Z12  = (z1, z2)
    c.CB = pk(a12, 0.0f);   // * Z12s = (z2, z1)
    c.CC = pk(a13, a24);    // * Z34  = (z3, z4)
    c.CD = pk(a14, a23);    // * Z34s = (z4, z3)
    c.Bm12 = pk(bm1, bm2);
    c.CE = pk(a33, a44);    // * Z34
    c.CF = pk(a34, 0.0f);   // * Z34s
    c.Bm34 = pk(bm3, bm4);
    c.Cbm0 = pk(bm0, 0.0f);
    c.CAB  = pk(a11 + a12, a22);   // (CA+CB) lane-wise, for d12=(hk,hk)

    const float4* w0 = (const float4*)(w + (size_t)b * 2 * TSTEPS);
    const float4* w1 = (const float4*)(w + (size_t)b * 2 * TSTEPS + TSTEPS);

    u64 X  = pk(1.0f, 0.0f);
    u64 Hh = pk(1.0f, 0.0f);
    u64 accQ2 = pk(0.0f, 0.0f);
    float accR = 0.0f, accT = 0.0f;
    // Step 0: dx==0 -> d==0, so the forwarding term vanishes identically and
    // delta is inert in the dynamics; phiS=-200 -> ex2->0 -> delta=rcp(1)=1
    // EXACTLY for the stage cost. No special case.
    float phiS = -200.0f;

    // ---- software prefetch pipeline: PD groups in registers ----
    float4 bA[PD], bB[PD];
#pragma unroll
    for (int d = 0; d < PD; ++d) { bA[d] = w0[d]; bB[d] = w1[d]; }

    // First PD groups (consume slot d, prefetch group PD+d)
#pragma unroll
    for (int d = 0; d < PD; ++d) {
        float4 wa = bA[d], wb = bB[d];
        bA[d] = w0[PD + d]; bB[d] = w1[PD + d];
        stepP<true>(c, wa.x, wb.x, X, Hh, phiS, accQ2, accR, accT);
        stepP<true>(c, wa.y, wb.y, X, Hh, phiS, accQ2, accR, accT);
        stepP<true>(c, wa.z, wb.z, X, Hh, phiS, accQ2, accR, accT);
        stepP<true>(c, wa.w, wb.w, X, Hh, phiS, accQ2, accR, accT);
    }

    // Main: consume slot d = group base+d, prefetch group base+PD+d
    for (int base = PD; base < NG - PD; base += PD) {
#pragma unroll
        for (int d = 0; d < PD; ++d) {
            float4 wa = bA[d], wb = bB[d];
            bA[d] = w0[base + PD + d];
            bB[d] = w1[base + PD + d];
            stepP<true>(c, wa.x, wb.x, X, Hh, phiS, accQ2, accR, accT);
            stepP<true>(c, wa.y, wb.y, X, Hh, phiS, accQ2, accR, accT);
            stepP<true>(c, wa.z, wb.z, X, Hh, phiS, accQ2, accR, accT);
            stepP<true>(c, wa.w, wb.w, X, Hh, phiS, accQ2, accR, accT);
        }
    }

    // Tail: groups NG-PD .. NG-1 from the buffers (static slots)
#pragma unroll
    for (int d = 0; d < PD - 1; ++d) {
        float4 wa = bA[d], wb = bB[d];
        stepP<true>(c, wa.x, wb.x, X, Hh, phiS, accQ2, accR, accT);
        stepP<true>(c, wa.y, wb.y, X, Hh, phiS, accQ2, accR, accT);
        stepP<true>(c, wa.z, wb.z, X, Hh, phiS, accQ2, accR, accT);
        stepP<true>(c, wa.w, wb.w, X, Hh, phiS, accQ2, accR, accT);
    }
    {   // last group: final step (i = T-1) updates state, adds no stage cost
        float4 wa = bA[PD - 1], wb = bB[PD - 1];
        stepP<true >(c, wa.x, wb.x, X, Hh, phiS, accQ2, accR, accT);
        stepP<true >(c, wa.y, wb.y, X, Hh, phiS, accQ2, accR, accT);
        stepP<true >(c, wa.z, wb.z, X, Hh, phiS, accQ2, accR, accT);
        stepP<false>(c, wa.w, wb.w, X, Hh, phiS, accQ2, accR, accT);
    }

    // J = Sigma x^T x + 0.1 Sigma u_s^2 + Sigma delta + terminal 10|x_T|^2
    float aq1, aq2; upk(aq1, aq2, accQ2);
    float J = aq1 + aq2;
    J = fmaf(0.1f, accR, J);
    J = J + accT;
    float x1, x2; upk(x1, x2, X);
    J = fmaf(10.0f * x1, x1, J);
    J = fmaf(10.0f * x2, x2, J);

    if (b < BSIZE) out[b] = J;
}

extern "C" void kernel_launch(void* const* d_in, const int* in_sizes, int n_in,
                              void* d_out, int out_size)
{
    const float* w  = (const float*)d_in[0];
    const float* K  = (const float*)d_in[1];
    const float* L  = (const float*)d_in[2];
    const float* M  = (const float*)d_in[3];
    const float* Mo = (const float*)d_in[4];
    float* out = (float*)d_out;

    // 8192 trajectories, 1 thread each; 128 blocks x 64 threads = 256 warps,
    // one warp per SMSP.
    cstr_traj_kernel<<<BSIZE / 64, 64>>>(w, K, L, M, Mo, out);
}

// round 16
// speedup vs baseline: 1.0081x; 1.0081x over previous
#include <cuda_runtime.h>

#define TSTEPS 2048
#define BSIZE  8192
#define HH     0.01f
#define NG     (TSTEPS / 4)   // 512 groups of 4 steps
#define PD     4              // prefetch distance (groups)

typedef unsigned long long u64;

__device__ __forceinline__ float ex2f(float x) {
    float y; asm("ex2.approx.ftz.f32 %0, %1;" : "=f"(y) : "f"(x)); return y;
}
__device__ __forceinline__ float rcpf(float x) {
    float y; asm("rcp.approx.ftz.f32 %0, %1;" : "=f"(y) : "f"(x)); return y;
}
__device__ __forceinline__ u64 pk(float lo, float hi) {
    u64 r; asm("mov.b64 %0, {%1, %2};" : "=l"(r) : "f"(lo), "f"(hi)); return r;
}
__device__ __forceinline__ void upk(float& lo, float& hi, u64 v) {
    asm("mov.b64 {%0, %1}, %2;" : "=f"(lo), "=f"(hi) : "l"(v));
}
__device__ __forceinline__ u64 fma2(u64 a, u64 b, u64 c) {
    u64 d; asm("fma.rn.f32x2 %0, %1, %2, %3;" : "=l"(d) : "l"(a), "l"(b), "l"(c)); return d;
}
__device__ __forceinline__ u64 add2(u64 a, u64 b) {
    u64 d; asm("add.rn.f32x2 %0, %1, %2;" : "=l"(d) : "l"(a), "l"(b)); return d;
}
__device__ __forceinline__ u64 mul2(u64 a, u64 b) {
    u64 d; asm("mul.rn.f32x2 %0, %1, %2;" : "=l"(d) : "l"(a), "l"(b)); return d;
}

struct CP {
    u64 NEG1, E2, HH2, HHb, Cp;
    // Lane-matched pairs (coeffs scaled by -log2e), proven in R13:
    //   q1(z) = a11 z1 + a12 z2 + a13 z3 + a14 z4 + bm1
    //   q2(z) = a22 z2 +        a23 z3 + a24 z4 + bm2
    //   q3(z) = a33 z3 + a34 z4 + bm3 ;  q4(z) = a44 z4 + bm4
    // packed with Z12=(z1,z2), Z12s=(z2,z1), Z34=(z3,z4), Z34s=(z4,z3):
    //   Q12 = Z12*CA + Z12s*CB + Z34*CC + Z34s*CD + Bm12
    //   Q34 = Z34*CE + Z34s*CF + Bm34
    u64 CA, CB, CC, CD, Bm12, CE, CF, Bm34, Cbm0;
    u64 CAB;            // CA + CB lane-wise = (a11+a12, a22) — for d=(hk,hk,..)
    float K1, K2;
};

// One step. delta = rcp(1 + ex2(phiS)), phiS loop-carried scalar.
// KEY: q(z_new) = q(zm) + delta * U*d  (matvec is linear; z_new = zm + delta*d)
// so BOTH trees (on zm and on d) run in the MUFU shadow. Post-rcp chain:
// DEL2 mov -> {X,Hh,Q12n,Q34n} (parallel fma2) -> PP inner -> PP outer -> fadd
// = ~21 cyc. Full chain ~57; slot floor ~62.
template<bool ADDSC>
__device__ __forceinline__ void stepP(const CP& c, float w1, float w2,
                                      u64& X, u64& Hh, float& phiS,
                                      u64& accQ2, float& accR, float& accT)
{
    float e = ex2f(phiS);                     // MUFU #1, issues first

    // ---- shadow geometry (zm, d and both trees fit in the MUFU shadows) ----
    u64 DX = fma2(Hh, c.NEG1, X);             // d34 = (dx1, dx2) = X - H
    float dx1, dx2; upk(dx1, dx2, DX);
    float h1, h2;   upk(h1, h2, Hh);
    float x1s, x2s; upk(x1s, x2s, X);
    u64 Xs = pk(x2s, x1s);

    float kuh = fmaf(c.K2, h2, c.K1 * h1);    // K . x_hat
    float kdx = fmaf(c.K2, dx2, c.K1 * dx1);  // K . (x - x_hat)
    float hkdx = 0.01f * kdx;                 // delta-coefficient of x'

    u64 W  = pk(w1, w2);
    u64 WC = add2(W, c.Cp);                   // + (h^2/2, -h^2)
    u64 T1 = fma2(X, c.E2, WC);               // 0.98*x + w + C
    u64 BASE = fma2(Xs, c.HH2, T1);           // + 0.01*x_swapped
    u64 KUH2 = pk(kuh, kuh);
    u64 BXu  = fma2(KUH2, c.HHb, BASE);       // zm12: x' = BXu + delta*hk
    u64 HKp  = pk(hkdx, hkdx);                // d12 (symmetric pair)

    // zm = (BXu, Hh_old), d = (HKp, DX): shadow swaps
    float bxu1, bxu2; upk(bxu1, bxu2, BXu);
    u64 BXuS = pk(bxu2, bxu1);
    u64 HhS  = pk(h2, h1);
    u64 DXs  = pk(dx2, dx1);

    // q(zm) = U*zm + m  (6 packed)
    u64 QZM12 = fma2(BXu, c.CA,
                fma2(BXuS, c.CB,
                fma2(Hh, c.CC,
                fma2(HhS, c.CD, c.Bm12))));
    u64 QZM34 = fma2(Hh, c.CE, fma2(HhS, c.CF, c.Bm34));
    // U*d (no m). d12s == d12 = (hk,hk) -> CA,CB merge into CAB. (5 packed)
    u64 UD12 = fma2(HKp, c.CAB, fma2(DX, c.CC, mul2(DXs, c.CD)));
    u64 UD34 = fma2(DX, c.CE, mul2(DXs, c.CF));

    if (ADDSC) {
        accQ2 = fma2(X, X, accQ2);            // packed sum of x^2
        float kx = kuh + kdx;                 // u_s = K . x (exact)
        accR = fmaf(kx, kx, accR);            // 0.1 applied once at the end
    }

    float den   = 1.0f + e;
    float delta = rcpf(den);                  // MUFU #2
    if (ADDSC) accT = accT + delta;           // off the chain

    // ---- post-rcp: broadcast, then 4 PARALLEL fma2, dot, horizontal ----
    u64 DEL2 = pk(delta, delta);
    X  = fma2(DEL2, HKp, BXu);                // new state
    Hh = fma2(DEL2, DX, Hh);
    u64 Q12n = fma2(DEL2, UD12, QZM12);       // q(z_new), forwarded
    u64 Q34n = fma2(DEL2, UD34, QZM34);
    u64 PP = fma2(X, Q12n, fma2(Hh, Q34n, c.Cbm0));
    float plo, phi_; upk(plo, phi_, PP);
    phiS = plo + phi_;                        // scalar carried into next step
}

__global__ void __launch_bounds__(64, 1) cstr_traj_kernel(
    const float* __restrict__ w,   // (B, 2, T)
    const float* __restrict__ K,   // (1, 2)
    const float* __restrict__ L,   // (4, 4)
    const float* __restrict__ M,   // (1, 4)
    const float* __restrict__ Mo,  // (1, 1)
    float* __restrict__ out)       // (B,)
{
    int b = blockIdx.x * blockDim.x + threadIdx.x;

    const float s = -1.44269504088896340736f;  // -log2(e), folded into phi
    float K1 = __ldg(K), K2 = __ldg(K + 1);
    float l[16];
#pragma unroll
    for (int i = 0; i < 16; i++) l[i] = __ldg(L + i);
    float a11 = s * l[0],           a22 = s * l[5];
    float a33 = s * l[10],          a44 = s * l[15];
    float a12 = s * (l[1] + l[4]),  a13 = s * (l[2] + l[8]);
    float a14 = s * (l[3] + l[12]), a23 = s * (l[6] + l[9]);
    float a24 = s * (l[7] + l[13]), a34 = s * (l[11] + l[14]);
    float bm1 = s * __ldg(M),       bm2 = s * __ldg(M + 1);
    float bm3 = s * __ldg(M + 2),   bm4 = s * __ldg(M + 3);
    float bm0 = s * __ldg(Mo);

    CP c;
    c.K1 = K1; c.K2 = K2;
    c.NEG1 = pk(-1.0f, -1.0f);
    c.E2   = pk(0.98f, 0.98f);
    c.HH2  = pk(HH, HH);
    c.HHb  = pk(HH, HH);
    c.Cp   = pk(0.5f * HH * HH, -HH * HH);      // (+h^2/2, -h^2)
    c.CA = pk(a11, a22);    // * Z12  = (z1, z2)
    c.CB = pk(a12, 0.0f);   // * Z12s = (z2, z1)
    c.CC = pk(a13, a24);    // * Z34  = (z3, z4)
    c.CD = pk(a14, a23);    // * Z34s = (z4, z3)
    c.Bm12 = pk(bm1, bm2);
    c.CE = pk(a33, a44);    // * Z34
    c.CF = pk(a34, 0.0f);   // * Z34s
    c.Bm34 = pk(bm3, bm4);
    c.Cbm0 = pk(bm0, 0.0f);
    c.CAB  = pk(a11 + a12, a22);   // (CA+CB) lane-wise, for d12=(hk,hk)

    const float4* w0 = (const float4*)(w + (size_t)b * 2 * TSTEPS);
    const float4* w1 = (const float4*)(w + (size_t)b * 2 * TSTEPS + TSTEPS);

    u64 X  = pk(1.0f, 0.0f);
    u64 Hh = pk(1.0f, 0.0f);
    u64 accQ2 = pk(0.0f, 0.0f);
    float accR = 0.0f, accT = 0.0f;
    // Step 0: dx==0 -> d==0, so the forwarding term vanishes identically and
    // delta is inert in the dynamics; phiS=-200 -> ex2->0 -> delta=rcp(1)=1
    // EXACTLY for the stage cost. No special case.
    float phiS = -200.0f;

    // ---- software prefetch pipeline: PD groups in registers ----
    float4 bA[PD], bB[PD];
#pragma unroll
    for (int d = 0; d < PD; ++d) { bA[d] = w0[d]; bB[d] = w1[d]; }

    // First PD groups (consume slot d, prefetch group PD+d)
#pragma unroll
    for (int d = 0; d < PD; ++d) {
        float4 wa = bA[d], wb = bB[d];
        bA[d] = w0[PD + d]; bB[d] = w1[PD + d];
        stepP<true>(c, wa.x, wb.x, X, Hh, phiS, accQ2, accR, accT);
        stepP<true>(c, wa.y, wb.y, X, Hh, phiS, accQ2, accR, accT);
        stepP<true>(c, wa.z, wb.z, X, Hh, phiS, accQ2, accR, accT);
        stepP<true>(c, wa.w, wb.w, X, Hh, phiS, accQ2, accR, accT);
    }

    // Main: consume slot d = group base+d, prefetch group base+PD+d
    for (int base = PD; base < NG - PD; base += PD) {
#pragma unroll
        for (int d = 0; d < PD; ++d) {
            float4 wa = bA[d], wb = bB[d];
            bA[d] = w0[base + PD + d];
            bB[d] = w1[base + PD + d];
            stepP<true>(c, wa.x, wb.x, X, Hh, phiS, accQ2, accR, accT);
            stepP<true>(c, wa.y, wb.y, X, Hh, phiS, accQ2, accR, accT);
            stepP<true>(c, wa.z, wb.z, X, Hh, phiS, accQ2, accR, accT);
            stepP<true>(c, wa.w, wb.w, X, Hh, phiS, accQ2, accR, accT);
        }
    }

    // Tail: groups NG-PD .. NG-1 from the buffers (static slots)
#pragma unroll
    for (int d = 0; d < PD - 1; ++d) {
        float4 wa = bA[d], wb = bB[d];
        stepP<true>(c, wa.x, wb.x, X, Hh, phiS, accQ2, accR, accT);
        stepP<true>(c, wa.y, wb.y, X, Hh, phiS, accQ2, accR, accT);
        stepP<true>(c, wa.z, wb.z, X, Hh, phiS, accQ2, accR, accT);
        stepP<true>(c, wa.w, wb.w, X, Hh, phiS, accQ2, accR, accT);
    }
    {   // last group: final step (i = T-1) updates state, adds no stage cost
        float4 wa = bA[PD - 1], wb = bB[PD - 1];
        stepP<true >(c, wa.x, wb.x, X, Hh, phiS, accQ2, accR, accT);
        stepP<true >(c, wa.y, wb.y, X, Hh, phiS, accQ2, accR, accT);
        stepP<true >(c, wa.z, wb.z, X, Hh, phiS, accQ2, accR, accT);
        stepP<false>(c, wa.w, wb.w, X, Hh, phiS, accQ2, accR, accT);
    }

    // J = Sigma x^T x + 0.1 Sigma u_s^2 + Sigma delta + terminal 10|x_T|^2
    float aq1, aq2; upk(aq1, aq2, accQ2);
    float J = aq1 + aq2;
    J = fmaf(0.1f, accR, J);
    J = J + accT;
    float x1, x2; upk(x1, x2, X);
    J = fmaf(10.0f * x1, x1, J);
    J = fmaf(10.0f * x2, x2, J);

    if (b < BSIZE) out[b] = J;
}

extern "C" void kernel_launch(void* const* d_in, const int* in_sizes, int n_in,
                              void* d_out, int out_size)
{
    const float* w  = (const float*)d_in[0];
    const float* K  = (const float*)d_in[1];
    const float* L  = (const float*)d_in[2];
    const float* M  = (const float*)d_in[3];
    const float* Mo = (const float*)d_in[4];
    float* out = (float*)d_out;

    // 8192 trajectories, 1 thread each; 128 blocks x 64 threads = 256 warps,
    // one warp per SMSP.
    cstr_traj_kernel<<<BSIZE / 64, 64>>>(w, K, L, M, Mo, out);
}

// round 17
// speedup vs baseline: 1.1928x; 1.1832x over previous
#include <cuda_runtime.h>

#define TSTEPS 2048
#define BSIZE  8192
#define HH     0.01f
#define NG     (TSTEPS / 4)   // 512 groups of 4 steps
#define PD     4              // prefetch distance (groups)

typedef unsigned long long u64;

__device__ __forceinline__ float ex2f(float x) {
    float y; asm("ex2.approx.ftz.f32 %0, %1;" : "=f"(y) : "f"(x)); return y;
}
__device__ __forceinline__ float rcpf(float x) {
    float y; asm("rcp.approx.ftz.f32 %0, %1;" : "=f"(y) : "f"(x)); return y;
}
__device__ __forceinline__ u64 pk(float lo, float hi) {
    u64 r; asm("mov.b64 %0, {%1, %2};" : "=l"(r) : "f"(lo), "f"(hi)); return r;
}
__device__ __forceinline__ void upk(float& lo, float& hi, u64 v) {
    asm("mov.b64 {%0, %1}, %2;" : "=f"(lo), "=f"(hi) : "l"(v));
}
__device__ __forceinline__ u64 fma2(u64 a, u64 b, u64 c) {
    u64 d; asm("fma.rn.f32x2 %0, %1, %2, %3;" : "=l"(d) : "l"(a), "l"(b), "l"(c)); return d;
}
__device__ __forceinline__ u64 add2(u64 a, u64 b) {
    u64 d; asm("add.rn.f32x2 %0, %1, %2;" : "=l"(d) : "l"(a), "l"(b)); return d;
}
__device__ __forceinline__ u64 mul2(u64 a, u64 b) {
    u64 d; asm("mul.rn.f32x2 %0, %1, %2;" : "=l"(d) : "l"(a), "l"(b)); return d;
}

struct CP {
    // R13's proven lane-matched tree pairs (coeffs scaled by -log2e):
    //   Q12 = Z12*CA + Z12s*CB + Z34*CC + Z34s*CD + Bm12   (q1,q2)
    //   Q34 = Z34*CE + Z34s*CF + Bm34                       (q3,q4)
    //   PP  = Z12*Q12 + (Z34*Q34 + (bm0,0)) ; phi = PP.lo + PP.hi (never summed:
    //   carried as two lanes, combined inside ex2 via 2^(a+b) = 2^a * 2^b)
    u64 CA, CB, CC, CD, Bm12, CE, CF, Bm34, Cbm0;
    float K1, K2;
};

// One step. delta = rcp(1 + 2^pLo * 2^pHi); (pLo,pHi) loop-carried lanes.
// Geometry: scalar immediate-form FMAs (rt=1), all in the MUFU shadow.
// delta applied with 4 scalar FMAs (no broadcast). Packed tree as in R13.
template<bool ADDSC>
__device__ __forceinline__ void stepS(const CP& c, float w1, float w2,
                                      float& x1, float& x2, float& h1, float& h2,
                                      u64& X, u64& Hh, float& pLo, float& pHi,
                                      u64& accQ2, float& accR, float& accT)
{
    const float C1 = 0.5f * HH * HH;     // +h^2/2 (collapsed RK4, x1 eq)
    const float C2 = -HH * HH;           // -h^2   (x2 eq)

    float eLo = ex2f(pLo);               // MUFU #1
    float eHi = ex2f(pHi);               // MUFU #2 (independent)

    // ---- shadow geometry: scalar, immediate multipliers (FFMA-imm rt=1) ----
    float dx1 = x1 - h1, dx2 = x2 - h2;
    float kuh = fmaf(c.K2, h2, c.K1 * h1);    // K . x_hat
    float kdx = fmaf(c.K2, dx2, c.K1 * dx1);  // K . (x - x_hat)
    float hk  = 0.01f * kdx;                  // delta-coefficient of x'
    float b1  = fmaf(0.98f, x1, fmaf(0.01f, x2, w1 + C1));
    float b2  = fmaf(0.01f, x1, fmaf(0.98f, x2, w2 + C2));
    float bu1 = fmaf(0.01f, kuh, b1);
    float bu2 = fmaf(0.01f, kuh, b2);

    if (ADDSC) {
        accQ2 = fma2(X, X, accQ2);            // packed sum of x^2 (current X)
        float kx = kuh + kdx;                 // u_s = K . x (exact)
        accR = fmaf(kx, kx, accR);            // 0.1 applied once at the end
    }

    float den   = fmaf(eLo, eHi, 1.0f);       // 1 + 2^(pLo+pHi)
    float delta = rcpf(den);                   // MUFU #3
    if (ADDSC) accT = accT + delta;            // off the chain

    // ---- post-rcp: 4 scalar FMAs, no broadcast, no unpack ----
    x1 = fmaf(delta, hk,  bu1);
    x2 = fmaf(delta, hk,  bu2);
    h1 = fmaf(delta, dx1, h1);
    h2 = fmaf(delta, dx2, h2);

    // ---- packed tree (R13 structure) on the new state ----
    X = pk(x1, x2);  Hh = pk(h1, h2);
    u64 Xs = pk(x2, x1), Hs = pk(h2, h1);
    u64 QA  = fma2(X,  c.CA, fma2(Xs, c.CB, c.Bm12));
    u64 QB  = fma2(Hh, c.CC, mul2(Hs, c.CD));
    u64 Q12 = add2(QA, QB);
    u64 Q34 = fma2(Hh, c.CE, fma2(Hs, c.CF, c.Bm34));
    u64 PP  = fma2(X, Q12, fma2(Hh, Q34, c.Cbm0));
    upk(pLo, pHi, PP);                         // carried as lanes; no fadd
}

__global__ void __launch_bounds__(64, 1) cstr_traj_kernel(
    const float* __restrict__ w,   // (B, 2, T)
    const float* __restrict__ K,   // (1, 2)
    const float* __restrict__ L,   // (4, 4)
    const float* __restrict__ M,   // (1, 4)
    const float* __restrict__ Mo,  // (1, 1)
    float* __restrict__ out)       // (B,)
{
    int b = blockIdx.x * blockDim.x + threadIdx.x;

    const float s = -1.44269504088896340736f;  // -log2(e), folded into phi
    float K1 = __ldg(K), K2 = __ldg(K + 1);
    float l[16];
#pragma unroll
    for (int i = 0; i < 16; i++) l[i] = __ldg(L + i);
    float a11 = s * l[0],           a22 = s * l[5];
    float a33 = s * l[10],          a44 = s * l[15];
    float a12 = s * (l[1] + l[4]),  a13 = s * (l[2] + l[8]);
    float a14 = s * (l[3] + l[12]), a23 = s * (l[6] + l[9]);
    float a24 = s * (l[7] + l[13]), a34 = s * (l[11] + l[14]);
    float bm1 = s * __ldg(M),       bm2 = s * __ldg(M + 1);
    float bm3 = s * __ldg(M + 2),   bm4 = s * __ldg(M + 3);
    float bm0 = s * __ldg(Mo);

    CP c;
    c.K1 = K1; c.K2 = K2;
    // Lane check (q1,q2): q1 = a11 x1 + a12 x2 + a13 h1 + a14 h2 + bm1
    //                     q2 = a22 x2 +   0 x1 + a24 h2 + a23 h1 + bm2
    c.CA = pk(a11, a22);    // * Z12  = (x1, x2)
    c.CB = pk(a12, 0.0f);   // * Z12s = (x2, x1)
    c.CC = pk(a13, a24);    // * Z34  = (h1, h2)
    c.CD = pk(a14, a23);    // * Z34s = (h2, h1)
    c.Bm12 = pk(bm1, bm2);
    // (q3,q4): q3 = a33 h1 + a34 h2 + bm3 ; q4 = a44 h2 + bm4
    c.CE = pk(a33, a44);
    c.CF = pk(a34, 0.0f);
    c.Bm34 = pk(bm3, bm4);
    c.Cbm0 = pk(bm0, 0.0f);

    const float4* w0 = (const float4*)(w + (size_t)b * 2 * TSTEPS);
    const float4* w1 = (const float4*)(w + (size_t)b * 2 * TSTEPS + TSTEPS);

    float x1 = 1.0f, x2 = 0.0f, h1 = 1.0f, h2 = 0.0f;
    u64 X  = pk(1.0f, 0.0f);
    u64 Hh = pk(1.0f, 0.0f);
    u64 accQ2 = pk(0.0f, 0.0f);
    float accR = 0.0f, accT = 0.0f;
    // Step 0: reference forces delta=1 with x_hat frozen. dx==0 makes delta
    // inert in the dynamics; (pLo,pHi)=(-200,0): ex2(-200)=0 (ftz), ex2(0)=1,
    // den = fma(0,1,1) = 1, delta = rcp(1) = 1 EXACTLY. No special case.
    float pLo = -200.0f, pHi = 0.0f;

    // ---- software prefetch pipeline: PD groups in registers ----
    float4 bA[PD], bB[PD];
#pragma unroll
    for (int d = 0; d < PD; ++d) { bA[d] = w0[d]; bB[d] = w1[d]; }

    // First PD groups (consume slot d, prefetch group PD+d)
#pragma unroll
    for (int d = 0; d < PD; ++d) {
        float4 wa = bA[d], wb = bB[d];
        bA[d] = w0[PD + d]; bB[d] = w1[PD + d];
        stepS<true>(c, wa.x, wb.x, x1, x2, h1, h2, X, Hh, pLo, pHi, accQ2, accR, accT);
        stepS<true>(c, wa.y, wb.y, x1, x2, h1, h2, X, Hh, pLo, pHi, accQ2, accR, accT);
        stepS<true>(c, wa.z, wb.z, x1, x2, h1, h2, X, Hh, pLo, pHi, accQ2, accR, accT);
        stepS<true>(c, wa.w, wb.w, x1, x2, h1, h2, X, Hh, pLo, pHi, accQ2, accR, accT);
    }

    // Main: consume slot d = group base+d, prefetch group base+PD+d
    for (int base = PD; base < NG - PD; base += PD) {
#pragma unroll
        for (int d = 0; d < PD; ++d) {
            float4 wa = bA[d], wb = bB[d];
            bA[d] = w0[base + PD + d];
            bB[d] = w1[base + PD + d];
            stepS<true>(c, wa.x, wb.x, x1, x2, h1, h2, X, Hh, pLo, pHi, accQ2, accR, accT);
            stepS<true>(c, wa.y, wb.y, x1, x2, h1, h2, X, Hh, pLo, pHi, accQ2, accR, accT);
            stepS<true>(c, wa.z, wb.z, x1, x2, h1, h2, X, Hh, pLo, pHi, accQ2, accR, accT);
            stepS<true>(c, wa.w, wb.w, x1, x2, h1, h2, X, Hh, pLo, pHi, accQ2, accR, accT);
        }
    }

    // Tail: groups NG-PD .. NG-1 from the buffers (static slots)
#pragma unroll
    for (int d = 0; d < PD - 1; ++d) {
        float4 wa = bA[d], wb = bB[d];
        stepS<true>(c, wa.x, wb.x, x1, x2, h1, h2, X, Hh, pLo, pHi, accQ2, accR, accT);
        stepS<true>(c, wa.y, wb.y, x1, x2, h1, h2, X, Hh, pLo, pHi, accQ2, accR, accT);
        stepS<true>(c, wa.z, wb.z, x1, x2, h1, h2, X, Hh, pLo, pHi, accQ2, accR, accT);
        stepS<true>(c, wa.w, wb.w, x1, x2, h1, h2, X, Hh, pLo, pHi, accQ2, accR, accT);
    }
    {   // last group: final step (i = T-1) updates state, adds no stage cost
        float4 wa = bA[PD - 1], wb = bB[PD - 1];
        stepS<true >(c, wa.x, wb.x, x1, x2, h1, h2, X, Hh, pLo, pHi, accQ2, accR, accT);
        stepS<true >(c, wa.y, wb.y, x1, x2, h1, h2, X, Hh, pLo, pHi, accQ2, accR, accT);
        stepS<true >(c, wa.z, wb.z, x1, x2, h1, h2, X, Hh, pLo, pHi, accQ2, accR, accT);
        stepS<false>(c, wa.w, wb.w, x1, x2, h1, h2, X, Hh, pLo, pHi, accQ2, accR, accT);
    }

    // J = Sigma x^T x + 0.1 Sigma u_s^2 + Sigma delta + terminal 10|x_T|^2
    float aq1, aq2; upk(aq1, aq2, accQ2);
    float J = aq1 + aq2;
    J = fmaf(0.1f, accR, J);
    J = J + accT;
    J = fmaf(10.0f * x1, x1, J);
    J = fmaf(10.0f * x2, x2, J);

    if (b < BSIZE) out[b] = J;
}

extern "C" void kernel_launch(void* const* d_in, const int* in_sizes, int n_in,
                              void* d_out, int out_size)
{
    const float* w  = (const float*)d_in[0];
    const float* K  = (const float*)d_in[1];
    const float* L  = (const float*)d_in[2];
    const float* M  = (const float*)d_in[3];
    const float* Mo = (const float*)d_in[4];
    float* out = (float*)d_out;

    // 8192 trajectories, 1 thread each; 128 blocks x 64 threads = 256 warps,
    // one warp per SMSP.
    cstr_traj_kernel<<<BSIZE / 64, 64>>>(w, K, L, M, Mo, out);
}